// round 14
// baseline (speedup 1.0000x reference)
#include <cuda_runtime.h>
#include <cuda_fp16.h>
#include <cstdint>

#define NUM_A 8
#define EDIM 128
#define OUTSTRIDE (NUM_A * EDIM)   // 1024 floats per batch row of edge/out
#define KC 32                      // K elements per pipeline chunk
#define CHPT 8                     // chunks per tile (K = 256)
#define NSTAGE 4
#define MTILE 128
#define THREADS 256                // 8 warps, each owning a 32x64 output tile
#define A_BYTES (MTILE * KC * 2)   // 8 KB fp16 A stage (128 rows x 64B)
#define B_RES_BYTES (EDIM * 256 * 2)       // 64 KB resident fused-weight tile
#define SMEM_TOTAL (B_RES_BYTES + NSTAGE * A_BYTES)   // 96 KB

// Fused weights fp16, combined K: g_Ph[a][j][k], k<128 img half, k>=128 edge half.
__device__ __half g_Ph[NUM_A * EDIM * 256];
__device__ float  g_cvec[NUM_A * EDIM];    // bias through projection

__device__ __forceinline__ void cp_async16(uint32_t dst, const void* src) {
    asm volatile("cp.async.cg.shared.global [%0], [%1], 16;" :: "r"(dst), "l"(src));
}
__device__ __forceinline__ void cp_commit() { asm volatile("cp.async.commit_group;"); }
__device__ __forceinline__ void cp_wait0() {
    asm volatile("cp.async.wait_group 0;");
}
__device__ __forceinline__ void ldsm_x4(uint32_t& r0, uint32_t& r1, uint32_t& r2, uint32_t& r3,
                                        uint32_t addr) {
    asm volatile("ldmatrix.sync.aligned.m8n8.x4.shared.b16 {%0,%1,%2,%3}, [%4];"
                 : "=r"(r0), "=r"(r1), "=r"(r2), "=r"(r3) : "r"(addr));
}
__device__ __forceinline__ uint32_t f16x2(float f0, float f1) {
    uint32_t d;
    asm("cvt.rn.f16x2.f32 %0, %1, %2;" : "=r"(d) : "f"(f1), "f"(f0));
    return d;
}
__device__ __forceinline__ void sts64(uint32_t addr, uint32_t r0, uint32_t r1) {
    asm volatile("st.shared.v2.b32 [%0], {%1,%2};" :: "r"(addr), "r"(r0), "r"(r1));
}
__device__ __forceinline__ void mma_f16(float* c, const uint32_t* a, uint32_t b0, uint32_t b1) {
    asm volatile("mma.sync.aligned.m16n8k16.row.col.f32.f16.f16.f32 "
                 "{%0,%1,%2,%3},{%4,%5,%6,%7},{%8,%9},{%0,%1,%2,%3};"
                 : "+f"(c[0]), "+f"(c[1]), "+f"(c[2]), "+f"(c[3])
                 : "r"(a[0]), "r"(a[1]), "r"(a[2]), "r"(a[3]), "r"(b0), "r"(b1));
}

// A-stage swizzle: 64B rows (32 fp16), 4x16B chunks; chunk XOR (row>>1)&3.
__device__ __forceinline__ uint32_t a_off(int row, int cbyte) {
    return (uint32_t)(row * 64 + ((((cbyte >> 4) ^ ((row >> 1) & 3)) << 4) | (cbyte & 15)));
}
// Resident-B swizzle: 512B rows (256 fp16), 32x16B chunks; chunk low3 XOR (j&7).
__device__ __forceinline__ uint32_t b_off(int j, int c16) {
    return (uint32_t)(j * 512 + (((c16 & ~7) | ((c16 ^ j) & 7)) << 4));
}

// ---------------------------------------------------------------------------
// Precompute fused weights (fp16, combined K) and cvec. 67 MFLOP, negligible.
// ---------------------------------------------------------------------------
__global__ void precompute_kernel(const float* __restrict__ W, const float* __restrict__ bvec,
                                  const float* __restrict__ proj) {
    const int a = blockIdx.x;
    const int j = blockIdx.y;
    const int k = threadIdx.x;   // 0..255
    const float* pa = proj + ((size_t)a * EDIM) * EDIM + j;   // proj[a][i][j], stride E
    float acc = 0.f, accC = 0.f;
#pragma unroll 8
    for (int i = 0; i < EDIM; i++) {
        float p = __ldg(pa + (size_t)i * EDIM);
        acc = fmaf(__ldg(W + i * 256 + k), p, acc);
        if (k == 0) accC = fmaf(__ldg(bvec + i), p, accC);
    }
    g_Ph[((size_t)a * EDIM + j) * 256 + k] = __float2half_rn(acc);
    if (k == 0) g_cvec[a * EDIM + j] = accC;
}

// ---------------------------------------------------------------------------
// RESIDENT-B persistent GEMM (round-11 champion) with DUAL-CHUNK iterations:
// one barrier covers two 32-K chunks (4 barriers/tile instead of 8), LDG for
// chunk g+4/g+5 issued two full phases before consumption, 8 outstanding
// LDG.128/thread. CTA = (a, slot), MTILE=128, 8 warps x 32x64, 2 CTAs/SM.
// ---------------------------------------------------------------------------
__global__ __launch_bounds__(THREADS, 2) void gnn_kernel(const float* __restrict__ img,
                                                         const float* __restrict__ edge,
                                                         float* __restrict__ out,
                                                         int ntiles_m) {
    extern __shared__ float smem[];
    const uint32_t smem_b = (uint32_t)__cvta_generic_to_shared(smem);
    const uint32_t bres = smem_b;                       // resident B
    const uint32_t astg = smem_b + B_RES_BYTES;         // A ring (4 stages)
    const int a = blockIdx.x;
    const int slot = blockIdx.y;
    const int nslot = gridDim.y;
    const int tid = threadIdx.x;
    const int lane = tid & 31;
    const int warp = tid >> 5;
    const int m0 = (warp & 3) * 32;    // warp row base within CTA tile
    const int n0 = (warp >> 2) * 64;   // warp col base within CTA tile

    // ---- Prologue: load resident B[a] (64KB) via cp.async ----
    {
        const __half* srcB = g_Ph + (size_t)a * EDIM * 256;
#pragma unroll
        for (int q = 0; q < 16; q++) {
            int id = tid + q * THREADS;    // 0..4095
            int j = id >> 5;
            int c16 = id & 31;
            cp_async16(bres + b_off(j, c16), srcB + (size_t)j * 256 + c16 * 8);
        }
        cp_commit();
    }

    const int my_tiles = (ntiles_m - slot + nslot - 1) / nslot;
    if (my_tiles <= 0) { cp_wait0(); return; }
    const int total_chunks = my_tiles * CHPT;   // multiple of 8 (even)

    float acc[2][8][4];
#pragma unroll
    for (int mt = 0; mt < 2; mt++)
#pragma unroll
        for (int nt = 0; nt < 8; nt++)
#pragma unroll
            for (int v = 0; v < 4; v++) acc[mt][nt][v] = 0.f;

    float4 regA[2][4];                 // two chunks staged in registers

    // LDG one A chunk (global chunk index g) into regA[r].
    auto ldg_chunk = [&](int g, int r) {
        const int mbase = (slot + (g >> 3) * nslot) * MTILE;
        const int kc = g & 7;
        const float* srcA;
        size_t strideA;
        if (kc < 4) { srcA = img + (size_t)mbase * EDIM + kc * KC;                     strideA = EDIM; }
        else        { srcA = edge + (size_t)mbase * OUTSTRIDE + a * EDIM + (kc - 4) * KC; strideA = OUTSTRIDE; }
        const int c4 = tid & 7;
        const int r0 = tid >> 3;
#pragma unroll
        for (int q = 0; q < 4; q++)
            regA[r][q] = *reinterpret_cast<const float4*>(srcA + (size_t)(r0 + 32 * q) * strideA + c4 * 4);
    };

    auto sts_chunk = [&](int s, int r) {
        const uint32_t abase = astg + s * A_BYTES;
        const int c4 = tid & 7;
        const int r0 = tid >> 3;
#pragma unroll
        for (int q = 0; q < 4; q++) {
            uint32_t p0 = f16x2(regA[r][q].x, regA[r][q].y);
            uint32_t p1 = f16x2(regA[r][q].z, regA[r][q].w);
            sts64(abase + a_off(r0 + 32 * q, c4 * 8), p0, p1);
        }
    };

    auto compute_chunk = [&](int s, int kc) {
        const uint32_t abase = astg + s * A_BYTES;
#pragma unroll
        for (int ks = 0; ks < 2; ks++) {   // 2 k16 steps per 32-wide chunk
            uint32_t afr[2][4];
#pragma unroll
            for (int mt = 0; mt < 2; mt++) {
                int r = m0 + mt * 16 + (lane & 15);
                int cb = ks * 32 + (lane >> 4) * 16;
                ldsm_x4(afr[mt][0], afr[mt][1], afr[mt][2], afr[mt][3],
                        abase + a_off(r, cb));
            }
#pragma unroll
            for (int ng = 0; ng < 4; ng++) {
                int blk = lane >> 3;                       // 0..3
                int jr = n0 + ng * 16 + (lane & 7) + ((blk & 2) ? 8 : 0);
                int c16 = kc * 4 + ks * 2 + (blk & 1);     // 16B chunk within 512B row
                uint32_t r0, r1, r2, r3;
                ldsm_x4(r0, r1, r2, r3, bres + b_off(jr, c16));
#pragma unroll
                for (int mt = 0; mt < 2; mt++) {
                    mma_f16(acc[mt][ng * 2],     afr[mt], r0, r1);
                    mma_f16(acc[mt][ng * 2 + 1], afr[mt], r2, r3);
                }
            }
        }
    };

    // A-ring prologue: chunks 0,1 -> regs; B wait; 0,1 -> smem; 2,3 -> regs.
    ldg_chunk(0, 0);
    ldg_chunk(1, 1);
    cp_wait0();                      // resident B landed
    sts_chunk(0, 0);
    sts_chunk(1, 1);
    ldg_chunk(2, 0);
    ldg_chunk(3, 1);

#pragma unroll 1
    for (int g = 0; g < total_chunks; g += 2) {
        __syncthreads();             // A stages g, g+1 (STS'd last iter) visible
        compute_chunk(g & 3, g & 7);
        if (g + 2 < total_chunks) sts_chunk((g + 2) & 3, 0);   // stage of chunk g-2: free
        compute_chunk((g + 1) & 3, (g + 1) & 7);
        if (g + 3 < total_chunks) sts_chunk((g + 3) & 3, 1);   // stage of chunk g-1: free
        if (g + 4 < total_chunks) ldg_chunk(g + 4, 0);
        if (g + 5 < total_chunks) ldg_chunk(g + 5, 1);

        if ((g & 7) == 6) {
            // Tile (g>>3) finished: register epilogue (no smem, no barrier).
            const int mbase = (slot + (g >> 3) * nslot) * MTILE;
            const float* cv = g_cvec + a * EDIM;
#pragma unroll
            for (int mt = 0; mt < 2; mt++) {
                int r0 = mbase + m0 + mt * 16 + (lane >> 2);
#pragma unroll
                for (int nt = 0; nt < 8; nt++) {
                    int col = n0 + (nt >> 1) * 16 + (nt & 1) * 8 + (lane & 3) * 2;
                    float b0 = __ldg(cv + col);
                    float b1 = __ldg(cv + col + 1);
                    float2 v0 = make_float2(acc[mt][nt][0] + b0, acc[mt][nt][1] + b1);
                    float2 v1 = make_float2(acc[mt][nt][2] + b0, acc[mt][nt][3] + b1);
                    size_t base0 = (size_t)r0 * OUTSTRIDE + a * EDIM + col;
                    size_t base1 = (size_t)(r0 + 8) * OUTSTRIDE + a * EDIM + col;
                    *reinterpret_cast<float2*>(out + base0) = v0;
                    *reinterpret_cast<float2*>(out + base1) = v1;
                    acc[mt][nt][0] = 0.f; acc[mt][nt][1] = 0.f;
                    acc[mt][nt][2] = 0.f; acc[mt][nt][3] = 0.f;
                }
            }
        }
    }
}

extern "C" void kernel_launch(void* const* d_in, const int* in_sizes, int n_in,
                              void* d_out, int out_size) {
    const float* img  = (const float*)d_in[0];   // [B, E]
    const float* edge = (const float*)d_in[1];   // [B, A, E]
    const float* W    = (const float*)d_in[2];   // [E, 2E]
    const float* bvec = (const float*)d_in[3];   // [E]
    const float* proj = (const float*)d_in[4];   // [A, E, E]
    const int Bn = in_sizes[0] / EDIM;
    const int ntiles_m = Bn / MTILE;             // 512

    precompute_kernel<<<dim3(NUM_A, EDIM), 256>>>(W, bvec, proj);

    int sms = 148;
    cudaDeviceGetAttribute(&sms, cudaDevAttrMultiProcessorCount, 0);
    int nslot = (2 * sms) / NUM_A;               // 37 slots for 148 SMs
    if (nslot < 1) nslot = 1;
    if (nslot > ntiles_m) nslot = ntiles_m;

    cudaFuncSetAttribute(gnn_kernel, cudaFuncAttributeMaxDynamicSharedMemorySize, SMEM_TOTAL);
    // CTA (a, slot): slot-aligned m-tile sweeps keep the 8 a-CTAs of a slot on
    // the same img/edge rows concurrently for L2/DRAM locality.
    gnn_kernel<<<dim3(NUM_A, nslot), THREADS, SMEM_TOTAL>>>(img, edge, (float*)d_out, ntiles_m);
}

// round 15
// speedup vs baseline: 1.0793x; 1.0793x over previous
#include <cuda_runtime.h>
#include <cuda_fp16.h>
#include <cstdint>

#define NUM_A 8
#define EDIM 128
#define OUTSTRIDE (NUM_A * EDIM)   // 1024 floats per batch row of edge/out
#define KC 32                      // K elements per pipeline chunk
#define CHPT 8                     // chunks per tile (K = 256)
#define NSTAGE 3
#define MTILE 128
#define THREADS 256                // 8 warps, each owning a 32x64 output tile
#define A_BYTES (MTILE * KC * 2)   // 8 KB fp16 A stage (128 rows x 64B)
#define B_RES_BYTES (EDIM * 256 * 2)       // 64 KB resident fused-weight tile
#define SMEM_TOTAL (B_RES_BYTES + NSTAGE * A_BYTES)   // 88 KB
#define JB 8                       // j-columns per precompute block

// Fused weights fp16, combined K: g_Ph[a][j][k], k<128 img half, k>=128 edge half.
__device__ __half g_Ph[NUM_A * EDIM * 256];
__device__ float  g_cvec[NUM_A * EDIM];    // bias through projection

__device__ __forceinline__ void cp_async16(uint32_t dst, const void* src) {
    asm volatile("cp.async.cg.shared.global [%0], [%1], 16;" :: "r"(dst), "l"(src));
}
__device__ __forceinline__ void cp_commit() { asm volatile("cp.async.commit_group;"); }
__device__ __forceinline__ void cp_wait0() {
    asm volatile("cp.async.wait_group 0;");
}
__device__ __forceinline__ void ldsm_x4(uint32_t& r0, uint32_t& r1, uint32_t& r2, uint32_t& r3,
                                        uint32_t addr) {
    asm volatile("ldmatrix.sync.aligned.m8n8.x4.shared.b16 {%0,%1,%2,%3}, [%4];"
                 : "=r"(r0), "=r"(r1), "=r"(r2), "=r"(r3) : "r"(addr));
}
__device__ __forceinline__ uint32_t f16x2(float f0, float f1) {
    uint32_t d;
    asm("cvt.rn.f16x2.f32 %0, %1, %2;" : "=r"(d) : "f"(f1), "f"(f0));
    return d;
}
__device__ __forceinline__ void sts64(uint32_t addr, uint32_t r0, uint32_t r1) {
    asm volatile("st.shared.v2.b32 [%0], {%1,%2};" :: "r"(addr), "r"(r0), "r"(r1));
}
__device__ __forceinline__ void mma_f16(float* c, const uint32_t* a, uint32_t b0, uint32_t b1) {
    asm volatile("mma.sync.aligned.m16n8k16.row.col.f32.f16.f16.f32 "
                 "{%0,%1,%2,%3},{%4,%5,%6,%7},{%8,%9},{%0,%1,%2,%3};"
                 : "+f"(c[0]), "+f"(c[1]), "+f"(c[2]), "+f"(c[3])
                 : "r"(a[0]), "r"(a[1]), "r"(a[2]), "r"(a[3]), "r"(b0), "r"(b1));
}

// A-stage swizzle: 64B rows (32 fp16), 4x16B chunks; chunk XOR (row>>1)&3.
__device__ __forceinline__ uint32_t a_off(int row, int cbyte) {
    return (uint32_t)(row * 64 + ((((cbyte >> 4) ^ ((row >> 1) & 3)) << 4) | (cbyte & 15)));
}
// Resident-B swizzle: 512B rows (256 fp16), 32x16B chunks; chunk low3 XOR (j&7).
__device__ __forceinline__ uint32_t b_off(int j, int c16) {
    return (uint32_t)(j * 512 + (((c16 & ~7) | ((c16 ^ j) & 7)) << 4));
}

// ---------------------------------------------------------------------------
// Precompute fused weights (fp16, combined K) and cvec — j-blocked.
// Block = (a, 8 j-columns): proj columns staged in smem (broadcast reads),
// each W row loaded ONCE and reused across the 8 j-accumulators.
// W L2 traffic 134MB -> 17MB; ~4-6us vs ~18us for the naive version.
// ---------------------------------------------------------------------------
__global__ void precompute_kernel(const float* __restrict__ W, const float* __restrict__ bvec,
                                  const float* __restrict__ proj) {
    __shared__ float pj[EDIM][JB];     // proj[a][i][j0+jj]
    __shared__ float bv[EDIM];
    const int a = blockIdx.x;
    const int j0 = blockIdx.y * JB;
    const int tid = threadIdx.x;       // 0..255 (= k)

    for (int idx = tid; idx < EDIM * JB; idx += 256) {
        int i = idx >> 3;
        int jj = idx & (JB - 1);
        pj[i][jj] = __ldg(proj + ((size_t)a * EDIM + i) * EDIM + j0 + jj);
    }
    if (tid < EDIM) bv[tid] = __ldg(bvec + tid);
    __syncthreads();

    float acc[JB];
#pragma unroll
    for (int jj = 0; jj < JB; jj++) acc[jj] = 0.f;
#pragma unroll 4
    for (int i = 0; i < EDIM; i++) {
        float w = __ldg(W + i * 256 + tid);
#pragma unroll
        for (int jj = 0; jj < JB; jj++) acc[jj] = fmaf(w, pj[i][jj], acc[jj]);
    }
#pragma unroll
    for (int jj = 0; jj < JB; jj++)
        g_Ph[((size_t)a * EDIM + j0 + jj) * 256 + tid] = __float2half_rn(acc[jj]);

    if (tid < JB) {
        float c = 0.f;
#pragma unroll 4
        for (int i = 0; i < EDIM; i++) c = fmaf(bv[i], pj[i][tid], c);
        g_cvec[a * EDIM + j0 + tid] = c;
    }
}

// ---------------------------------------------------------------------------
// RESIDENT-B persistent GEMM (round-11 champion, unchanged). CTA = (a, slot);
// B[a] (64KB fp16) loaded into smem ONCE, then loop over m-tiles. Main loop
// has NO cp.async: A streams LDG fp32 -> cvt f16x2 -> STS fp16 (3-stage ring,
// rolled across tile boundaries), B fragments ldsm from the resident tile.
// 8 warps x 32x64 tiles, 2 CTAs/SM.
// ---------------------------------------------------------------------------
__global__ __launch_bounds__(THREADS, 2) void gnn_kernel(const float* __restrict__ img,
                                                         const float* __restrict__ edge,
                                                         float* __restrict__ out,
                                                         int ntiles_m) {
    extern __shared__ float smem[];
    const uint32_t smem_b = (uint32_t)__cvta_generic_to_shared(smem);
    const uint32_t bres = smem_b;                       // resident B
    const uint32_t astg = smem_b + B_RES_BYTES;         // A ring
    const int a = blockIdx.x;
    const int slot = blockIdx.y;
    const int nslot = gridDim.y;
    const int tid = threadIdx.x;
    const int lane = tid & 31;
    const int warp = tid >> 5;
    const int m0 = (warp & 3) * 32;    // warp row base within CTA tile
    const int n0 = (warp >> 2) * 64;   // warp col base within CTA tile

    // ---- Prologue: load resident B[a] (64KB) via cp.async ----
    {
        const __half* srcB = g_Ph + (size_t)a * EDIM * 256;
#pragma unroll
        for (int q = 0; q < 16; q++) {
            int id = tid + q * THREADS;    // 0..4095
            int j = id >> 5;
            int c16 = id & 31;
            cp_async16(bres + b_off(j, c16), srcB + (size_t)j * 256 + c16 * 8);
        }
        cp_commit();
    }

    const int my_tiles = (ntiles_m - slot + nslot - 1) / nslot;
    if (my_tiles <= 0) { cp_wait0(); return; }
    const int total_chunks = my_tiles * CHPT;

    float acc[2][8][4];
#pragma unroll
    for (int mt = 0; mt < 2; mt++)
#pragma unroll
        for (int nt = 0; nt < 8; nt++)
#pragma unroll
            for (int v = 0; v < 4; v++) acc[mt][nt][v] = 0.f;

    float4 regA[4];

    // LDG one A chunk (global chunk index g): tile = slot + (g/8)*nslot.
    auto ldg_chunk = [&](int g) {
        const int mbase = (slot + (g >> 3) * nslot) * MTILE;
        const int kc = g & 7;
        const float* srcA;
        size_t strideA;
        if (kc < 4) { srcA = img + (size_t)mbase * EDIM + kc * KC;                     strideA = EDIM; }
        else        { srcA = edge + (size_t)mbase * OUTSTRIDE + a * EDIM + (kc - 4) * KC; strideA = OUTSTRIDE; }
        const int c4 = tid & 7;
        const int r0 = tid >> 3;
#pragma unroll
        for (int q = 0; q < 4; q++)
            regA[q] = *reinterpret_cast<const float4*>(srcA + (size_t)(r0 + 32 * q) * strideA + c4 * 4);
    };

    auto sts_chunk = [&](int s) {
        const uint32_t abase = astg + s * A_BYTES;
        const int c4 = tid & 7;
        const int r0 = tid >> 3;
#pragma unroll
        for (int q = 0; q < 4; q++) {
            uint32_t p0 = f16x2(regA[q].x, regA[q].y);
            uint32_t p1 = f16x2(regA[q].z, regA[q].w);
            sts64(abase + a_off(r0 + 32 * q, c4 * 8), p0, p1);
        }
    };

    auto compute_chunk = [&](int s, int kc) {
        const uint32_t abase = astg + s * A_BYTES;
#pragma unroll
        for (int ks = 0; ks < 2; ks++) {   // 2 k16 steps per 32-wide chunk
            uint32_t afr[2][4];
#pragma unroll
            for (int mt = 0; mt < 2; mt++) {
                int r = m0 + mt * 16 + (lane & 15);
                int cb = ks * 32 + (lane >> 4) * 16;
                ldsm_x4(afr[mt][0], afr[mt][1], afr[mt][2], afr[mt][3],
                        abase + a_off(r, cb));
            }
#pragma unroll
            for (int ng = 0; ng < 4; ng++) {
                int blk = lane >> 3;                       // 0..3
                int jr = n0 + ng * 16 + (lane & 7) + ((blk & 2) ? 8 : 0);
                int c16 = kc * 4 + ks * 2 + (blk & 1);     // 16B chunk within 512B row
                uint32_t r0, r1, r2, r3;
                ldsm_x4(r0, r1, r2, r3, bres + b_off(jr, c16));
#pragma unroll
                for (int mt = 0; mt < 2; mt++) {
                    mma_f16(acc[mt][ng * 2],     afr[mt], r0, r1);
                    mma_f16(acc[mt][ng * 2 + 1], afr[mt], r2, r3);
                }
            }
        }
    };

    // Prologue of the A ring: chunk0 -> regs; B wait; chunk0 -> smem; chunk1 -> regs.
    ldg_chunk(0);
    cp_wait0();                      // resident B landed
    sts_chunk(0);
    if (total_chunks > 1) ldg_chunk(1);

#pragma unroll 1
    for (int g = 0; g < total_chunks; g++) {
        __syncthreads();             // A stage g (STS'd last iter) visible
        compute_chunk(g % NSTAGE, g & 7);
        if (g + 1 < total_chunks) sts_chunk((g + 1) % NSTAGE);
        if (g + 2 < total_chunks) ldg_chunk(g + 2);

        if ((g & 7) == 7) {
            // Tile finished: register epilogue (no smem, no barrier needed).
            const int mbase = (slot + (g >> 3) * nslot) * MTILE;
            const float* cv = g_cvec + a * EDIM;
#pragma unroll
            for (int mt = 0; mt < 2; mt++) {
                int r0 = mbase + m0 + mt * 16 + (lane >> 2);
#pragma unroll
                for (int nt = 0; nt < 8; nt++) {
                    int col = n0 + (nt >> 1) * 16 + (nt & 1) * 8 + (lane & 3) * 2;
                    float b0 = __ldg(cv + col);
                    float b1 = __ldg(cv + col + 1);
                    float2 v0 = make_float2(acc[mt][nt][0] + b0, acc[mt][nt][1] + b1);
                    float2 v1 = make_float2(acc[mt][nt][2] + b0, acc[mt][nt][3] + b1);
                    size_t base0 = (size_t)r0 * OUTSTRIDE + a * EDIM + col;
                    size_t base1 = (size_t)(r0 + 8) * OUTSTRIDE + a * EDIM + col;
                    *reinterpret_cast<float2*>(out + base0) = v0;
                    *reinterpret_cast<float2*>(out + base1) = v1;
                    acc[mt][nt][0] = 0.f; acc[mt][nt][1] = 0.f;
                    acc[mt][nt][2] = 0.f; acc[mt][nt][3] = 0.f;
                }
            }
        }
    }
}

extern "C" void kernel_launch(void* const* d_in, const int* in_sizes, int n_in,
                              void* d_out, int out_size) {
    const float* img  = (const float*)d_in[0];   // [B, E]
    const float* edge = (const float*)d_in[1];   // [B, A, E]
    const float* W    = (const float*)d_in[2];   // [E, 2E]
    const float* bvec = (const float*)d_in[3];   // [E]
    const float* proj = (const float*)d_in[4];   // [A, E, E]
    const int Bn = in_sizes[0] / EDIM;
    const int ntiles_m = Bn / MTILE;             // 512

    precompute_kernel<<<dim3(NUM_A, EDIM / JB), 256>>>(W, bvec, proj);

    int sms = 148;
    cudaDeviceGetAttribute(&sms, cudaDevAttrMultiProcessorCount, 0);
    int nslot = (2 * sms) / NUM_A;               // 37 slots for 148 SMs
    if (nslot < 1) nslot = 1;
    if (nslot > ntiles_m) nslot = ntiles_m;

    cudaFuncSetAttribute(gnn_kernel, cudaFuncAttributeMaxDynamicSharedMemorySize, SMEM_TOTAL);
    // CTA (a, slot): slot-aligned m-tile sweeps keep the 8 a-CTAs of a slot on
    // the same img/edge rows concurrently for L2/DRAM locality.
    gnn_kernel<<<dim3(NUM_A, nslot), THREADS, SMEM_TOTAL>>>(img, edge, (float*)d_out, ntiles_m);
}